// round 15
// baseline (speedup 1.0000x reference)
#include <cuda_runtime.h>
#include <cuda_bf16.h>
#include <cstdint>

// out[b,t,o] = (cummean_t x)[b,t,:] . W[t,:,o]
// B=4, T=1024, D=256, O=256. All fp32.
// Single fused kernel, 512 blocks x 128 threads, all co-resident.
// Barrier-free dataflow: seg8/seg64 readiness flags; each block polls only
// its own dependency set, so low-t0 blocks start the DRAM-bound W mainloop
// immediately and the HBM pipe never idles.

#define BB 4
#define TT 1024
#define DD 256
#define OO 256

#define STAGES 5
#define DCHUNK 4                 // d-rows per stage
#define NCHUNK (DD / DCHUNK)     // 64
#define NBLK (TT / 2)            // 512

__device__ float g_seg8[BB * 128 * DD];   // 512 KB: 8-row sums
__device__ float g_seg64[BB * 16 * DD];   // 64 KB: 64-row sums
__device__ unsigned g_f8[BB * 128];       // seg8 ready flags
__device__ unsigned g_f64[BB * 16];       // seg64 ready flags
__device__ unsigned g_cnt64[BB * 16];     // fold election counters
__device__ unsigned g_done;               // end-of-kernel reset election

__device__ __forceinline__ unsigned ld_acq(const unsigned* p) {
    unsigned v;
    asm volatile("ld.acquire.gpu.u32 %0, [%1];" : "=r"(v) : "l"(p));
    return v;
}

__device__ __forceinline__ void fma4(float4& acc, float s, const float4& v) {
    acc.x = fmaf(s, v.x, acc.x);
    acc.y = fmaf(s, v.y, acc.y);
    acc.z = fmaf(s, v.z, acc.z);
    acc.w = fmaf(s, v.w, acc.w);
}

__device__ __forceinline__ void add4(float4& a, const float4& v) {
    a.x += v.x; a.y += v.y; a.z += v.z; a.w += v.w;
}

// ILP-4 batched sum of n float4s strided by `stride` float4s.
__device__ __forceinline__ float4 sum_strided(const float4* p, int n, int stride) {
    float4 a0 = make_float4(0.f, 0.f, 0.f, 0.f);
    float4 a1 = a0, a2 = a0, a3 = a0;
    int i = 0;
    for (; i + 4 <= n; i += 4) {
        float4 v0 = p[(size_t)(i + 0) * stride];
        float4 v1 = p[(size_t)(i + 1) * stride];
        float4 v2 = p[(size_t)(i + 2) * stride];
        float4 v3 = p[(size_t)(i + 3) * stride];
        add4(a0, v0); add4(a1, v1); add4(a2, v2); add4(a3, v3);
    }
    for (; i < n; ++i)
        add4(a0, p[(size_t)i * stride]);
    add4(a0, a1); add4(a2, a3); add4(a0, a2);
    return a0;
}

__device__ __forceinline__ void cp16(void* smem_dst, const void* gmem_src) {
    uint32_t s = (uint32_t)__cvta_generic_to_shared(smem_dst);
    asm volatile("cp.async.cg.shared.global [%0], [%1], 16;\n"
                 :: "r"(s), "l"(gmem_src));
}

__global__ __launch_bounds__(128) void k_fused(const float* __restrict__ x,
                                               const float* __restrict__ W,
                                               float* __restrict__ out) {
    __shared__ float4 ws[STAGES][2][DCHUNK][OO / 4];  // 40 KB
    __shared__ float4 cm_s[2][BB][DD / 4];            // 8 KB (aliased in A)
    __shared__ int sh_elected;
    __shared__ int sh_last;

    int tid = threadIdx.x;
    int t0 = blockIdx.x * 2;
    int tg = tid >> 6;        // 0..1
    int o4 = tid & 63;        // float4 O-column

    const float4* W4 = reinterpret_cast<const float4*>(W);
    const float4* x4 = reinterpret_cast<const float4*>(x);

    auto issue = [&](int st, int ch) {
#pragma unroll
        for (int k = 0; k < 4; ++k) {
            int slot = tid + k * 128;          // 0..511
            int tg_ = slot >> 8;
            int dd  = (slot >> 6) & (DCHUNK - 1);
            int oo  = slot & 63;
            const float4* src = W4 + ((size_t)(t0 + tg_) * DD +
                                      (ch * DCHUNK + dd)) * (OO / 4) + oo;
            cp16(&ws[st][tg_][dd][oo], src);
        }
    };

    // ---- Phase A: seg8 for (bscan, s). x loads first (critical path). ----
    int bscan = blockIdx.x >> 7;    // 0..3
    int s = blockIdx.x & 127;       // 0..127
    int grp = bscan * 16 + (s >> 3);
    int d4 = tid & 63;
    int q  = tid >> 6;              // half-segment (4 rows each)

    const float4* xp = x4 + (size_t)(bscan * TT + s * 8 + q * 4) * (DD / 4) + d4;
    float4 v0 = xp[0 * (DD / 4)];
    float4 v1 = xp[1 * (DD / 4)];
    float4 v2 = xp[2 * (DD / 4)];
    float4 v3 = xp[3 * (DD / 4)];

    // W cp.async prologue (drains behind the scan work)
#pragma unroll
    for (int p = 0; p < STAGES - 1; ++p) {
        issue(p, p);
        asm volatile("cp.async.commit_group;\n" ::: "memory");
    }

    {
        float4 (*qs)[64] = reinterpret_cast<float4(*)[64]>(&cm_s[0][0][0]);
        float4 h = v0;
        add4(h, v1); add4(h, v2); add4(h, v3);
        qs[q][d4] = h;
        __syncthreads();
        if (q == 0) {
            float4 r = qs[0][d4];
            add4(r, qs[1][d4]);
            reinterpret_cast<float4*>(g_seg8)
                [(size_t)(bscan * 128 + s) * (DD / 4) + d4] = r;
        }
        __threadfence();
        if (tid == 0) {
            atomicExch(&g_f8[bscan * 128 + s], 1u);          // publish seg8
            unsigned c = atomicAdd(&g_cnt64[grp], 1u);       // fold election
            sh_elected = (c == 7u);
        }
        __syncthreads();

        // elected (last) producer of a 64-group folds seg8 -> seg64
        if (sh_elected) {
            __threadfence();  // see all 8 members' seg8 stores
            if (tid < 64) {
                const float4* S8 = reinterpret_cast<const float4*>(g_seg8) +
                                   (size_t)(bscan * 128 + (s >> 3) * 8) * (DD / 4) + tid;
                float4 r = sum_strided(S8, 8, DD / 4);
                reinterpret_cast<float4*>(g_seg64)
                    [(size_t)grp * (DD / 4) + tid] = r;
            }
            __syncthreads();
            __threadfence();
            if (tid == 0)
                atomicExch(&g_f64[grp], 1u);
        }
    }

    // ---- Poll ONLY this block's dependency set ----
    {
        int s64 = t0 >> 6;                 // full 64-groups needed per b
        int k8e = t0 >> 3;                 // full seg8s needed per b
        int n64 = 4 * s64;                 // <= 60
        int n8c = 4 * (k8e - 8 * s64);     // <= 28
        for (int i = tid; i < n64; i += 128) {
            const unsigned* f = &g_f64[(i & 3) * 16 + (i >> 2)];
            while (ld_acq(f) == 0u) { __nanosleep(32); }
        }
        for (int i = tid; i < n8c; i += 128) {
            const unsigned* f = &g_f8[(i & 3) * 128 + 8 * s64 + (i >> 2)];
            while (ld_acq(f) == 0u) { __nanosleep(32); }
        }
        __syncthreads();
    }

    // ---- Phase B: private cm for this block's 2 t-rows, 4 b's ----
    {
        int p = tid >> 6;                      // 0..1 -> handles b = 2p, 2p+1
        int s64 = t0 >> 6;
        int k8e = t0 >> 3;
        int nx  = (t0 & 7) + 1;                // x rows [8*k8e .. t0]
        float i0 = 1.0f / (float)(t0 + 1);
        float i1 = 1.0f / (float)(t0 + 2);

#pragma unroll
        for (int bi = 0; bi < 2; ++bi) {
            int b = 2 * p + bi;
            const float4* S64 = reinterpret_cast<const float4*>(g_seg64) +
                                (size_t)(b * 16) * (DD / 4) + d4;
            const float4* S8  = reinterpret_cast<const float4*>(g_seg8) +
                                (size_t)(b * 128 + 8 * s64) * (DD / 4) + d4;
            const float4* X   = x4 + (size_t)(b * TT + 8 * k8e) * (DD / 4) + d4;

            float4 acc = sum_strided(S64, s64, DD / 4);
            add4(acc, sum_strided(S8, k8e - 8 * s64, DD / 4));
            add4(acc, sum_strided(X, nx, DD / 4));      // inclusive to t0
            float4 r1 = acc;
            add4(r1, X[(size_t)nx * (DD / 4)]);         // + row t0+1

            float4 c0, c1;
            c0.x = acc.x * i0; c0.y = acc.y * i0; c0.z = acc.z * i0; c0.w = acc.w * i0;
            c1.x = r1.x * i1;  c1.y = r1.y * i1;  c1.z = r1.z * i1;  c1.w = r1.w * i1;
            cm_s[0][b][d4] = c0;
            cm_s[1][b][d4] = c1;
        }
    }
    __syncthreads();

    // ---- GEMM mainloop (DRAM-bound streamer; unchanged) ----
    float4 a0 = make_float4(0.f, 0.f, 0.f, 0.f);
    float4 a1 = a0, a2 = a0, a3 = a0;

    int st = 0;
    for (int ch = 0; ch < NCHUNK; ++ch) {
        asm volatile("cp.async.wait_group %0;\n" :: "n"(STAGES - 2) : "memory");
        __syncthreads();

        float4 c0 = cm_s[tg][0][ch];
        float4 c1 = cm_s[tg][1][ch];
        float4 c2 = cm_s[tg][2][ch];
        float4 c3 = cm_s[tg][3][ch];

        {
            float4 w = ws[st][tg][0][o4];
            fma4(a0, c0.x, w); fma4(a1, c1.x, w); fma4(a2, c2.x, w); fma4(a3, c3.x, w);
        }
        {
            float4 w = ws[st][tg][1][o4];
            fma4(a0, c0.y, w); fma4(a1, c1.y, w); fma4(a2, c2.y, w); fma4(a3, c3.y, w);
        }
        {
            float4 w = ws[st][tg][2][o4];
            fma4(a0, c0.z, w); fma4(a1, c1.z, w); fma4(a2, c2.z, w); fma4(a3, c3.z, w);
        }
        {
            float4 w = ws[st][tg][3][o4];
            fma4(a0, c0.w, w); fma4(a1, c1.w, w); fma4(a2, c2.w, w); fma4(a3, c3.w, w);
        }

        int stn = st + STAGES - 1;
        if (stn >= STAGES) stn -= STAGES;
        int nxt = ch + STAGES - 1;
        if (nxt < NCHUNK)
            issue(stn, nxt);
        asm volatile("cp.async.commit_group;\n" ::: "memory");

        if (++st == STAGES) st = 0;
    }

    int t = t0 + tg;
    float4* op = reinterpret_cast<float4*>(out);
    __stcs(&op[(size_t)(0 * TT + t) * (OO / 4) + o4], a0);
    __stcs(&op[(size_t)(1 * TT + t) * (OO / 4) + o4], a1);
    __stcs(&op[(size_t)(2 * TT + t) * (OO / 4) + o4], a2);
    __stcs(&op[(size_t)(3 * TT + t) * (OO / 4) + o4], a3);

    // ---- last-finishing block resets all flags for the next graph replay --
    __syncthreads();
    if (tid == 0) {
        __threadfence();
        unsigned d = atomicAdd(&g_done, 1u);
        sh_last = (d == (unsigned)(NBLK - 1));
    }
    __syncthreads();
    if (sh_last) {
        for (int i = tid; i < BB * 128; i += 128) g_f8[i] = 0u;
        if (tid < BB * 16) { g_f64[tid] = 0u; g_cnt64[tid] = 0u; }
        __syncthreads();
        if (tid == 0) g_done = 0u;
    }
}

extern "C" void kernel_launch(void* const* d_in, const int* in_sizes, int n_in,
                              void* d_out, int out_size) {
    const float* x = (const float*)d_in[0];   // (B,T,D)
    const float* W = (const float*)d_in[1];   // (T,D,O)
    float* out = (float*)d_out;               // (B,T,O)

    k_fused<<<NBLK, 128>>>(x, W, out);
}

// round 16
// speedup vs baseline: 1.1627x; 1.1627x over previous
#include <cuda_runtime.h>
#include <cuda_bf16.h>
#include <cstdint>

// out[b,t,o] = (cummean_t x)[b,t,:] . W[t,:,o]
// B=4, T=1024, D=256, O=256. All fp32.
// 3 kernels, kernel boundaries are the only GPU-wide syncs:
//   k_seg8: 8-row partial sums of x            (reads x once)
//   k_fold: seg8 -> seg64                      (tiny)
//   k_gemm: private cm from seg64/seg8/x tail, then DRAM-bound W streamer.

#define BB 4
#define TT 1024
#define DD 256
#define OO 256

#define STAGES 5
#define DCHUNK 4                 // d-rows per stage
#define NCHUNK (DD / DCHUNK)     // 64
#define NBLK (TT / 2)            // 512

__device__ float g_seg8[BB * 128 * DD];   // 512 KB: 8-row sums
__device__ float g_seg64[BB * 16 * DD];   // 64 KB: 64-row sums

__device__ __forceinline__ void fma4(float4& acc, float s, const float4& v) {
    acc.x = fmaf(s, v.x, acc.x);
    acc.y = fmaf(s, v.y, acc.y);
    acc.z = fmaf(s, v.z, acc.z);
    acc.w = fmaf(s, v.w, acc.w);
}

__device__ __forceinline__ void add4(float4& a, const float4& v) {
    a.x += v.x; a.y += v.y; a.z += v.z; a.w += v.w;
}

// ILP-4 batched sum of n float4s strided by `stride` float4s.
__device__ __forceinline__ float4 sum_strided(const float4* p, int n, int stride) {
    float4 a0 = make_float4(0.f, 0.f, 0.f, 0.f);
    float4 a1 = a0, a2 = a0, a3 = a0;
    int i = 0;
    for (; i + 4 <= n; i += 4) {
        float4 v0 = p[(size_t)(i + 0) * stride];
        float4 v1 = p[(size_t)(i + 1) * stride];
        float4 v2 = p[(size_t)(i + 2) * stride];
        float4 v3 = p[(size_t)(i + 3) * stride];
        add4(a0, v0); add4(a1, v1); add4(a2, v2); add4(a3, v3);
    }
    for (; i < n; ++i)
        add4(a0, p[(size_t)i * stride]);
    add4(a0, a1); add4(a2, a3); add4(a0, a2);
    return a0;
}

__device__ __forceinline__ void cp16(void* smem_dst, const void* gmem_src) {
    uint32_t s = (uint32_t)__cvta_generic_to_shared(smem_dst);
    asm volatile("cp.async.cg.shared.global [%0], [%1], 16;\n"
                 :: "r"(s), "l"(gmem_src));
}

// ---------------------------------------------------------------------------
// Kernel 1: seg8. 512 blocks x 128 threads; block j -> (b = j>>7, s = j&127).
// Threads (q = tid>>6, d4 = tid&63) each sum 4 rows; smem-reduce the halves.
// ---------------------------------------------------------------------------
__global__ __launch_bounds__(128) void k_seg8(const float* __restrict__ x) {
    __shared__ float4 qs[2][64];

    int b = blockIdx.x >> 7;
    int s = blockIdx.x & 127;
    int d4 = threadIdx.x & 63;
    int q  = threadIdx.x >> 6;

    const float4* xp = reinterpret_cast<const float4*>(x) +
                       (size_t)(b * TT + s * 8 + q * 4) * (DD / 4) + d4;
    float4 h = xp[0 * (DD / 4)];
    float4 v1 = xp[1 * (DD / 4)];
    float4 v2 = xp[2 * (DD / 4)];
    float4 v3 = xp[3 * (DD / 4)];
    add4(h, v1); add4(h, v2); add4(h, v3);
    qs[q][d4] = h;
    __syncthreads();

    if (q == 0) {
        float4 r = qs[0][d4];
        add4(r, qs[1][d4]);
        reinterpret_cast<float4*>(g_seg8)
            [(size_t)(b * 128 + s) * (DD / 4) + d4] = r;
    }
}

// ---------------------------------------------------------------------------
// Kernel 2: fold seg8 -> seg64. 32 blocks x 128 threads = 4096 jobs.
// job j: b = j>>10, k = (j>>6)&15, dj = j&63; sums 8 consecutive seg8.
// ---------------------------------------------------------------------------
__global__ __launch_bounds__(128) void k_fold() {
    int j = blockIdx.x * 128 + threadIdx.x;   // 0..4095
    int b = j >> 10;
    int k = (j >> 6) & 15;
    int dj = j & 63;
    const float4* S8 = reinterpret_cast<const float4*>(g_seg8) +
                       (size_t)(b * 128 + k * 8) * (DD / 4) + dj;
    float4 r = sum_strided(S8, 8, DD / 4);
    reinterpret_cast<float4*>(g_seg64)[(size_t)(b * 16 + k) * (DD / 4) + dj] = r;
}

// ---------------------------------------------------------------------------
// Kernel 3: GEMM. 512 blocks x 128 threads. W cp.async prologue first, then
// private cm reconstruction (<=31 L2 loads per (p,d4) job), then the
// convoyed DRAM-bound mainloop.
// ---------------------------------------------------------------------------
__global__ __launch_bounds__(128) void k_gemm(const float* __restrict__ x,
                                              const float* __restrict__ W,
                                              float* __restrict__ out) {
    __shared__ float4 ws[STAGES][2][DCHUNK][OO / 4];  // 40 KB
    __shared__ float4 cm_s[2][BB][DD / 4];            // 8 KB

    int tid = threadIdx.x;
    int t0 = blockIdx.x * 2;
    int tg = tid >> 6;        // 0..1
    int o4 = tid & 63;        // float4 O-column
    int d4 = tid & 63;

    const float4* W4 = reinterpret_cast<const float4*>(W);
    const float4* x4 = reinterpret_cast<const float4*>(x);

    auto issue = [&](int st, int ch) {
#pragma unroll
        for (int k = 0; k < 4; ++k) {
            int slot = tid + k * 128;          // 0..511
            int tg_ = slot >> 8;
            int dd  = (slot >> 6) & (DCHUNK - 1);
            int oo  = slot & 63;
            const float4* src = W4 + ((size_t)(t0 + tg_) * DD +
                                      (ch * DCHUNK + dd)) * (OO / 4) + oo;
            cp16(&ws[st][tg_][dd][oo], src);
        }
    };

    // W prologue first: starts DRAM streaming immediately
#pragma unroll
    for (int p = 0; p < STAGES - 1; ++p) {
        issue(p, p);
        asm volatile("cp.async.commit_group;\n" ::: "memory");
    }

    // Private cm reconstruction: thread (p = tid>>6) handles b = 2p, 2p+1.
    {
        int p = tid >> 6;
        int s64 = t0 >> 6;                 // full 64-row groups (<=15)
        int k8e = t0 >> 3;                 // full 8-row segments
        int rem8 = k8e - 8 * s64;          // leftover seg8 (<=7)
        int nx  = (t0 & 7) + 1;            // x rows [8*k8e .. t0] (1,3,5,7)
        float i0 = 1.0f / (float)(t0 + 1);
        float i1 = 1.0f / (float)(t0 + 2);

#pragma unroll
        for (int bi = 0; bi < 2; ++bi) {
            int b = 2 * p + bi;
            const float4* S64 = reinterpret_cast<const float4*>(g_seg64) +
                                (size_t)(b * 16) * (DD / 4) + d4;
            const float4* S8  = reinterpret_cast<const float4*>(g_seg8) +
                                (size_t)(b * 128 + 8 * s64) * (DD / 4) + d4;
            const float4* X   = x4 + (size_t)(b * TT + 8 * k8e) * (DD / 4) + d4;

            float4 acc = sum_strided(S64, s64, DD / 4);
            add4(acc, sum_strided(S8, rem8, DD / 4));
            add4(acc, sum_strided(X, nx, DD / 4));      // inclusive to t0
            float4 r1 = acc;
            add4(r1, X[(size_t)nx * (DD / 4)]);         // + row t0+1

            float4 c0, c1;
            c0.x = acc.x * i0; c0.y = acc.y * i0; c0.z = acc.z * i0; c0.w = acc.w * i0;
            c1.x = r1.x * i1;  c1.y = r1.y * i1;  c1.z = r1.z * i1;  c1.w = r1.w * i1;
            cm_s[0][b][d4] = c0;
            cm_s[1][b][d4] = c1;
        }
    }
    __syncthreads();

    // DRAM-bound convoyed mainloop
    float4 a0 = make_float4(0.f, 0.f, 0.f, 0.f);
    float4 a1 = a0, a2 = a0, a3 = a0;

    int st = 0;
    for (int ch = 0; ch < NCHUNK; ++ch) {
        asm volatile("cp.async.wait_group %0;\n" :: "n"(STAGES - 2) : "memory");
        __syncthreads();

        float4 c0 = cm_s[tg][0][ch];
        float4 c1 = cm_s[tg][1][ch];
        float4 c2 = cm_s[tg][2][ch];
        float4 c3 = cm_s[tg][3][ch];

        {
            float4 w = ws[st][tg][0][o4];
            fma4(a0, c0.x, w); fma4(a1, c1.x, w); fma4(a2, c2.x, w); fma4(a3, c3.x, w);
        }
        {
            float4 w = ws[st][tg][1][o4];
            fma4(a0, c0.y, w); fma4(a1, c1.y, w); fma4(a2, c2.y, w); fma4(a3, c3.y, w);
        }
        {
            float4 w = ws[st][tg][2][o4];
            fma4(a0, c0.z, w); fma4(a1, c1.z, w); fma4(a2, c2.z, w); fma4(a3, c3.z, w);
        }
        {
            float4 w = ws[st][tg][3][o4];
            fma4(a0, c0.w, w); fma4(a1, c1.w, w); fma4(a2, c2.w, w); fma4(a3, c3.w, w);
        }

        int stn = st + STAGES - 1;
        if (stn >= STAGES) stn -= STAGES;
        int nxt = ch + STAGES - 1;
        if (nxt < NCHUNK)
            issue(stn, nxt);
        asm volatile("cp.async.commit_group;\n" ::: "memory");

        if (++st == STAGES) st = 0;
    }

    int t = t0 + tg;
    float4* op = reinterpret_cast<float4*>(out);
    __stcs(&op[(size_t)(0 * TT + t) * (OO / 4) + o4], a0);
    __stcs(&op[(size_t)(1 * TT + t) * (OO / 4) + o4], a1);
    __stcs(&op[(size_t)(2 * TT + t) * (OO / 4) + o4], a2);
    __stcs(&op[(size_t)(3 * TT + t) * (OO / 4) + o4], a3);
}

extern "C" void kernel_launch(void* const* d_in, const int* in_sizes, int n_in,
                              void* d_out, int out_size) {
    const float* x = (const float*)d_in[0];   // (B,T,D)
    const float* W = (const float*)d_in[1];   // (T,D,O)
    float* out = (float*)d_out;               // (B,T,O)

    k_seg8<<<NBLK, 128>>>(x);
    k_fold<<<32, 128>>>();
    k_gemm<<<NBLK, 128>>>(x, W, out);
}

// round 17
// speedup vs baseline: 1.1994x; 1.0316x over previous
#include <cuda_runtime.h>
#include <cuda_bf16.h>
#include <cstdint>

// out[b,t,o] = (cummean_t x)[b,t,:] . W[t,:,o]
// B=4, T=1024, D=256, O=256. All fp32.
// 2 kernels, kernel boundary is the only GPU-wide sync:
//   k_sums: per-64-row block computes 8x seg8 sums AND the seg64 sum.
//   k_gemm: private cm from seg64/seg8/x tail, then DRAM-bound W streamer.

#define BB 4
#define TT 1024
#define DD 256
#define OO 256

#define STAGES 5
#define DCHUNK 4                 // d-rows per stage
#define NCHUNK (DD / DCHUNK)     // 64
#define NBLK (TT / 2)            // 512

__device__ float g_seg8[BB * 128 * DD];   // 512 KB: 8-row sums
__device__ float g_seg64[BB * 16 * DD];   // 64 KB: 64-row sums

__device__ __forceinline__ void fma4(float4& acc, float s, const float4& v) {
    acc.x = fmaf(s, v.x, acc.x);
    acc.y = fmaf(s, v.y, acc.y);
    acc.z = fmaf(s, v.z, acc.z);
    acc.w = fmaf(s, v.w, acc.w);
}

__device__ __forceinline__ void add4(float4& a, const float4& v) {
    a.x += v.x; a.y += v.y; a.z += v.z; a.w += v.w;
}

// ILP-4 batched sum of n float4s strided by `stride` float4s.
__device__ __forceinline__ float4 sum_strided(const float4* p, int n, int stride) {
    float4 a0 = make_float4(0.f, 0.f, 0.f, 0.f);
    float4 a1 = a0, a2 = a0, a3 = a0;
    int i = 0;
    for (; i + 4 <= n; i += 4) {
        float4 v0 = p[(size_t)(i + 0) * stride];
        float4 v1 = p[(size_t)(i + 1) * stride];
        float4 v2 = p[(size_t)(i + 2) * stride];
        float4 v3 = p[(size_t)(i + 3) * stride];
        add4(a0, v0); add4(a1, v1); add4(a2, v2); add4(a3, v3);
    }
    for (; i < n; ++i)
        add4(a0, p[(size_t)i * stride]);
    add4(a0, a1); add4(a2, a3); add4(a0, a2);
    return a0;
}

__device__ __forceinline__ void cp16(void* smem_dst, const void* gmem_src) {
    uint32_t s = (uint32_t)__cvta_generic_to_shared(smem_dst);
    asm volatile("cp.async.cg.shared.global [%0], [%1], 16;\n"
                 :: "r"(s), "l"(gmem_src));
}

// ---------------------------------------------------------------------------
// Kernel 1: k_sums. 64 blocks x 256 threads; block = (b = bid>>4, k = bid&15)
// covering rows [k*64, k*64+64). Thread (q = tid>>6 in 0..3, d4 = tid&63)
// loads its 16 rows in two ILP-8 batches, emits 2 seg8 sums, and the block
// smem-reduces the four 16-row partials into the seg64 sum. One pass over x.
// ---------------------------------------------------------------------------
__global__ __launch_bounds__(256) void k_sums(const float* __restrict__ x) {
    __shared__ float4 qs[4][64];

    int b = blockIdx.x >> 4;
    int k = blockIdx.x & 15;
    int d4 = threadIdx.x & 63;
    int q  = threadIdx.x >> 6;   // 0..3, 16 rows each

    const float4* xp = reinterpret_cast<const float4*>(x) +
                       (size_t)(b * TT + k * 64 + q * 16) * (DD / 4) + d4;
    float4* S8 = reinterpret_cast<float4*>(g_seg8);

    float4 s64acc = make_float4(0.f, 0.f, 0.f, 0.f);
#pragma unroll
    for (int j = 0; j < 2; ++j) {           // two seg8 groups of 8 rows
        const float4* p = xp + (size_t)(j * 8) * (DD / 4);
        float4 v0 = p[0 * (DD / 4)];
        float4 v1 = p[1 * (DD / 4)];
        float4 v2 = p[2 * (DD / 4)];
        float4 v3 = p[3 * (DD / 4)];
        float4 v4 = p[4 * (DD / 4)];
        float4 v5 = p[5 * (DD / 4)];
        float4 v6 = p[6 * (DD / 4)];
        float4 v7 = p[7 * (DD / 4)];
        add4(v0, v1); add4(v2, v3); add4(v4, v5); add4(v6, v7);
        add4(v0, v2); add4(v4, v6); add4(v0, v4);
        // global seg8 index: k*8 + q*2 + j
        S8[(size_t)(b * 128 + k * 8 + q * 2 + j) * (DD / 4) + d4] = v0;
        add4(s64acc, v0);
    }
    qs[q][d4] = s64acc;
    __syncthreads();

    if (q == 0) {
        float4 r = qs[0][d4];
        add4(r, qs[1][d4]); add4(r, qs[2][d4]); add4(r, qs[3][d4]);
        reinterpret_cast<float4*>(g_seg64)
            [(size_t)(b * 16 + k) * (DD / 4) + d4] = r;
    }
}

// ---------------------------------------------------------------------------
// Kernel 2: GEMM. 512 blocks x 128 threads. W cp.async prologue first, then
// private cm reconstruction (<=31 L2 loads per (p,d4) job), then the
// convoyed DRAM-bound mainloop.
// ---------------------------------------------------------------------------
__global__ __launch_bounds__(128) void k_gemm(const float* __restrict__ x,
                                              const float* __restrict__ W,
                                              float* __restrict__ out) {
    __shared__ float4 ws[STAGES][2][DCHUNK][OO / 4];  // 40 KB
    __shared__ float4 cm_s[2][BB][DD / 4];            // 8 KB

    int tid = threadIdx.x;
    int t0 = blockIdx.x * 2;
    int tg = tid >> 6;        // 0..1
    int o4 = tid & 63;        // float4 O-column
    int d4 = tid & 63;

    const float4* W4 = reinterpret_cast<const float4*>(W);
    const float4* x4 = reinterpret_cast<const float4*>(x);

    auto issue = [&](int st, int ch) {
#pragma unroll
        for (int k = 0; k < 4; ++k) {
            int slot = tid + k * 128;          // 0..511
            int tg_ = slot >> 8;
            int dd  = (slot >> 6) & (DCHUNK - 1);
            int oo  = slot & 63;
            const float4* src = W4 + ((size_t)(t0 + tg_) * DD +
                                      (ch * DCHUNK + dd)) * (OO / 4) + oo;
            cp16(&ws[st][tg_][dd][oo], src);
        }
    };

    // W prologue first: starts DRAM streaming immediately
#pragma unroll
    for (int p = 0; p < STAGES - 1; ++p) {
        issue(p, p);
        asm volatile("cp.async.commit_group;\n" ::: "memory");
    }

    // Private cm reconstruction: thread (p = tid>>6) handles b = 2p, 2p+1.
    {
        int p = tid >> 6;
        int s64 = t0 >> 6;                 // full 64-row groups (<=15)
        int k8e = t0 >> 3;                 // full 8-row segments
        int rem8 = k8e - 8 * s64;          // leftover seg8 (<=7)
        int nx  = (t0 & 7) + 1;            // x rows [8*k8e .. t0] (1,3,5,7)
        float i0 = 1.0f / (float)(t0 + 1);
        float i1 = 1.0f / (float)(t0 + 2);

#pragma unroll
        for (int bi = 0; bi < 2; ++bi) {
            int b = 2 * p + bi;
            const float4* S64 = reinterpret_cast<const float4*>(g_seg64) +
                                (size_t)(b * 16) * (DD / 4) + d4;
            const float4* S8  = reinterpret_cast<const float4*>(g_seg8) +
                                (size_t)(b * 128 + 8 * s64) * (DD / 4) + d4;
            const float4* X   = x4 + (size_t)(b * TT + 8 * k8e) * (DD / 4) + d4;

            float4 acc = sum_strided(S64, s64, DD / 4);
            add4(acc, sum_strided(S8, rem8, DD / 4));
            add4(acc, sum_strided(X, nx, DD / 4));      // inclusive to t0
            float4 r1 = acc;
            add4(r1, X[(size_t)nx * (DD / 4)]);         // + row t0+1

            float4 c0, c1;
            c0.x = acc.x * i0; c0.y = acc.y * i0; c0.z = acc.z * i0; c0.w = acc.w * i0;
            c1.x = r1.x * i1;  c1.y = r1.y * i1;  c1.z = r1.z * i1;  c1.w = r1.w * i1;
            cm_s[0][b][d4] = c0;
            cm_s[1][b][d4] = c1;
        }
    }
    __syncthreads();

    // DRAM-bound convoyed mainloop
    float4 a0 = make_float4(0.f, 0.f, 0.f, 0.f);
    float4 a1 = a0, a2 = a0, a3 = a0;

    int st = 0;
    for (int ch = 0; ch < NCHUNK; ++ch) {
        asm volatile("cp.async.wait_group %0;\n" :: "n"(STAGES - 2) : "memory");
        __syncthreads();

        float4 c0 = cm_s[tg][0][ch];
        float4 c1 = cm_s[tg][1][ch];
        float4 c2 = cm_s[tg][2][ch];
        float4 c3 = cm_s[tg][3][ch];

        {
            float4 w = ws[st][tg][0][o4];
            fma4(a0, c0.x, w); fma4(a1, c1.x, w); fma4(a2, c2.x, w); fma4(a3, c3.x, w);
        }
        {
            float4 w = ws[st][tg][1][o4];
            fma4(a0, c0.y, w); fma4(a1, c1.y, w); fma4(a2, c2.y, w); fma4(a3, c3.y, w);
        }
        {
            float4 w = ws[st][tg][2][o4];
            fma4(a0, c0.z, w); fma4(a1, c1.z, w); fma4(a2, c2.z, w); fma4(a3, c3.z, w);
        }
        {
            float4 w = ws[st][tg][3][o4];
            fma4(a0, c0.w, w); fma4(a1, c1.w, w); fma4(a2, c2.w, w); fma4(a3, c3.w, w);
        }

        int stn = st + STAGES - 1;
        if (stn >= STAGES) stn -= STAGES;
        int nxt = ch + STAGES - 1;
        if (nxt < NCHUNK)
            issue(stn, nxt);
        asm volatile("cp.async.commit_group;\n" ::: "memory");

        if (++st == STAGES) st = 0;
    }

    int t = t0 + tg;
    float4* op = reinterpret_cast<float4*>(out);
    __stcs(&op[(size_t)(0 * TT + t) * (OO / 4) + o4], a0);
    __stcs(&op[(size_t)(1 * TT + t) * (OO / 4) + o4], a1);
    __stcs(&op[(size_t)(2 * TT + t) * (OO / 4) + o4], a2);
    __stcs(&op[(size_t)(3 * TT + t) * (OO / 4) + o4], a3);
}

extern "C" void kernel_launch(void* const* d_in, const int* in_sizes, int n_in,
                              void* d_out, int out_size) {
    const float* x = (const float*)d_in[0];   // (B,T,D)
    const float* W = (const float*)d_in[1];   // (T,D,O)
    float* out = (float*)d_out;               // (B,T,O)

    k_sums<<<BB * 16, 256>>>(x);
    k_gemm<<<NBLK, 128>>>(x, W, out);
}